// round 15
// baseline (speedup 1.0000x reference)
#include <cuda_runtime.h>
#include <math.h>
#include <stdint.h>

#define N_ATOMS 30000
#define N_EDGES 480000
#define H 128
#define R 50
#define NB 3
#define NEX 64
#define CUTOFF 10.0f
#define PI_F 3.14159265358979323846f

#define TILE_A 128
#define N_ATILES ((N_ATOMS + TILE_A - 1) / TILE_A)  // 235

// ---- bf16 edge kernel constants ----
#define ETILE 128
#define N_ETC (N_EDGES / ETILE)   // 3750
#define EK1 64
#define EBS 136
#define EA1S 72
#define EA2S 136
#define EB1  0
#define EB2  (EB1 + EK1 * EBS * 2)        // 17408
#define EA1  (EB2 + 128 * EBS * 2)        // 52224
#define EA2_ (EA1 + 128 * EA1S * 2)       // 70656
#define ECS  (EA2_ + 128 * EA2S * 2)      // 105472 (2x512B double-buffered)
#define ESS  (ECS + 1024)
#define ETS  (ESS + 1024)
#define EB1V (ETS + 1024)
#define EB2V (EB1V + 512)
#define SMB_EDGE (EB2V + 512)             // 109568 B -> 2 CTAs/SM

// ---- bf16 node kernel constants ----
#define NBS 136
#define NW1 0
#define NW2 (NW1 + 128 * NBS * 2)
#define NW3 (NW2 + 128 * NBS * 2)
#define NA  (NW3 + 128 * NBS * 2)
#define NB1V (NA + 128 * NBS * 2)
#define NB2V (NB1V + 512)
#define NB3V (NB2V + 512)                 // bias for GEMM3 (zeros or padded out_b1)
#define NW2V (NB3V + 512)                 // padded out_w2 (out mode)
#define SMB_UPD (NW2V + 512)
#define LW  0
#define LA  (LW + 128 * NBS * 2)
#define LZB (LA + 128 * NBS * 2)
#define SMB_LIN1 (LZB + 512)

#define REDV2(p, a, b) \
    asm volatile("red.global.add.v2.f32 [%0], {%1,%2};" \
                 :: "l"(p), "f"(a), "f"(b) : "memory")
#define MMA_BF16(acc, a, b0, b1) \
    asm volatile("mma.sync.aligned.m16n8k16.row.col.f32.bf16.bf16.f32 " \
                 "{%0,%1,%2,%3},{%4,%5,%6,%7},{%8,%9},{%0,%1,%2,%3};" \
                 : "+f"((acc)[0]), "+f"((acc)[1]), "+f"((acc)[2]), "+f"((acc)[3]) \
                 : "r"((a)[0]), "r"((a)[1]), "r"((a)[2]), "r"((a)[3]), "r"(b0), "r"(b1))
#define LDMX4(r, addr) \
    asm volatile("ldmatrix.sync.aligned.m8n8.x4.shared.b16 {%0,%1,%2,%3}, [%4];" \
                 : "=r"((r)[0]), "=r"((r)[1]), "=r"((r)[2]), "=r"((r)[3]) : "r"(addr))
#define LDMX4T(r, addr) \
    asm volatile("ldmatrix.sync.aligned.m8n8.x4.trans.shared.b16 {%0,%1,%2,%3}, [%4];" \
                 : "=r"((r)[0]), "=r"((r)[1]), "=r"((r)[2]), "=r"((r)[3]) : "r"(addr))
#define PACK_BF16X2(res, lo, hi) \
    asm("cvt.rn.satfinite.bf16x2.f32 %0, %1, %2;" : "=r"(res) : "f"(hi), "f"(lo))

__device__ __forceinline__ float ftanh(float x) {
    float e = __expf(2.0f * x);
    return fmaf(-2.0f, __frcp_rn(e + 1.0f), 1.0f);
}
__device__ __forceinline__ uint32_t smem_u32(const void* p) {
    uint32_t a;
    asm("{ .reg .u64 t; cvta.to.shared.u64 t, %1; cvt.u32.u64 %0, t; }" : "=r"(a) : "l"(p));
    return a;
}

// ---------------- device scratch (allocation-free) ----------------
__device__ float g_d[N_EDGES];
__device__ float g_C[N_EDGES];
__device__ float g_x[N_ATOMS * H];
__device__ float g_h[N_ATOMS * H];
__device__ float g_agg[N_ATOMS * H];

// ---- shared bf16 GEMM mainloop ----
template <int KSTEPS>
__device__ __forceinline__ void bf16_gemm(uint32_t aA0, uint32_t aA1,
                                          uint32_t aB0, uint32_t aB1, int bstep,
                                          const float* bias, int nb, int t,
                                          float acc[2][4][4]) {
#pragma unroll
    for (int mt = 0; mt < 2; mt++)
#pragma unroll
        for (int j = 0; j < 4; j++) {
            int c0 = nb + j * 8 + 2 * t;
            acc[mt][j][0] = bias[c0]; acc[mt][j][1] = bias[c0 + 1];
            acc[mt][j][2] = bias[c0]; acc[mt][j][3] = bias[c0 + 1];
        }
#pragma unroll
    for (int ks = 0; ks < KSTEPS; ks++) {
        uint32_t a0[4], a1[4], f0[4], f1[4];
        LDMX4(a0, aA0 + ks * 32);
        LDMX4(a1, aA1 + ks * 32);
        LDMX4T(f0, aB0 + ks * bstep);
        LDMX4T(f1, aB1 + ks * bstep);
        MMA_BF16(acc[0][0], a0, f0[0], f0[1]);
        MMA_BF16(acc[0][1], a0, f0[2], f0[3]);
        MMA_BF16(acc[0][2], a0, f1[0], f1[1]);
        MMA_BF16(acc[0][3], a0, f1[2], f1[3]);
        MMA_BF16(acc[1][0], a1, f0[0], f0[1]);
        MMA_BF16(acc[1][1], a1, f0[2], f0[3]);
        MMA_BF16(acc[1][2], a1, f1[0], f1[1]);
        MMA_BF16(acc[1][3], a1, f1[2], f1[3]);
    }
}

__device__ __forceinline__ void fill_wbf16(char* smem, int off,
                                           const float* __restrict__ W, int tid) {
    for (int i = tid; i < 128 * 64; i += 512) {
        int k = i >> 6, n = (i & 63) * 2;
        uint32_t p; PACK_BF16X2(p, W[k * H + n], W[k * H + n + 1]);
        *(uint32_t*)(smem + off + (k * NBS + n) * 2) = p;
    }
}

__device__ __forceinline__ void fill_abf16(char* smem, int off,
                                           const float* __restrict__ src,
                                           int a0, int tid) {
    for (int i = tid; i < 128 * 64; i += 512) {
        int r = i >> 6, n = (i & 63) * 2;
        int a = a0 + r;
        float lo = 0.f, hi = 0.f;
        if (a < N_ATOMS) { lo = src[(size_t)a * H + n]; hi = src[(size_t)a * H + n + 1]; }
        uint32_t p; PACK_BF16X2(p, lo, hi);
        *(uint32_t*)(smem + off + (r * NBS + n) * 2) = p;
    }
}

// ---------------- geometry: distances + cutoff ----------------
__global__ void geom_kernel(const float* __restrict__ pos,
                            const int* __restrict__ ei) {
    int e = blockIdx.x * blockDim.x + threadIdx.x;
    if (e >= N_EDGES) return;
    int s = ei[e];
    int t = ei[N_EDGES + e];
    float dx = pos[3 * s + 0] - pos[3 * t + 0];
    float dy = pos[3 * s + 1] - pos[3 * t + 1];
    float dz = pos[3 * s + 2] - pos[3 * t + 2];
    float d = sqrtf(dx * dx + dy * dy + dz * dz + 1e-12f);
    g_d[e] = d;
    g_C[e] = (d < CUTOFF) ? 0.5f * (cosf(d * PI_F / CUTOFF) + 1.0f) : 0.0f;
}

// ------- lin1 + fused embedding gather + agg zero (block 0 only) -------
__global__ __launch_bounds__(512) void lin1_bf16(const int* __restrict__ types,
                                                 const float* __restrict__ emb,
                                                 const float* __restrict__ W) {
    extern __shared__ char smem[];
    float* zb = (float*)(smem + LZB);
    const uint32_t sb = smem_u32(smem);
    const int tid = threadIdx.x;
    const int wid = tid >> 5, lane = tid & 31;
    const int g = lane >> 2, t = lane & 3;
    const int mb = (wid & 3) * 32, nb = (wid >> 2) * 32;
    const int lrow = lane & 15, lk8 = (lane >> 4) << 3;

    fill_wbf16(smem, LW, W, tid);
    if (tid < 128) zb[tid] = 0.0f;
    int a0 = blockIdx.x * TILE_A;
    // embedding gather -> A tile (bf16) + g_x (fp32) fused
    for (int i = tid; i < 128 * 64; i += 512) {
        int r = i >> 6, n = (i & 63) * 2;
        int a = a0 + r;
        float lo = 0.f, hi = 0.f;
        if (a < N_ATOMS) {
            int ty = types[a];
            lo = emb[(size_t)ty * H + n]; hi = emb[(size_t)ty * H + n + 1];
            float2 w; w.x = lo; w.y = hi;
            *(float2*)(g_x + (size_t)a * H + n) = w;
        }
        uint32_t p; PACK_BF16X2(p, lo, hi);
        *(uint32_t*)(smem + LA + (r * NBS + n) * 2) = p;
    }
    // zero agg for this tile range
    for (int i = tid; i < TILE_A * 32; i += 512) {
        int r = i >> 5, c = i & 31;
        if (a0 + r < N_ATOMS) {
            float4 z; z.x = z.y = z.z = z.w = 0.f;
            ((float4*)g_agg)[(size_t)(a0 + r) * 32 + c] = z;
        }
    }
    __syncthreads();

    uint32_t aA0 = sb + LA + ((mb + lrow) * NBS + lk8) * 2;
    uint32_t aA1 = sb + LA + ((mb + 16 + lrow) * NBS + lk8) * 2;
    uint32_t aB0 = sb + LW + (lrow * NBS + nb + lk8) * 2;
    uint32_t aB1 = sb + LW + (lrow * NBS + nb + 16 + lk8) * 2;

    float acc[2][4][4];
    bf16_gemm<8>(aA0, aA1, aB0, aB1, 16 * NBS * 2, zb, nb, t, acc);

#pragma unroll
    for (int mt = 0; mt < 2; mt++)
#pragma unroll
        for (int half = 0; half < 2; half++) {
            int row = mb + mt * 16 + half * 8 + g;
            if (a0 + row < N_ATOMS) {
                float* hp = g_h + (size_t)(a0 + row) * H;
#pragma unroll
                for (int j = 0; j < 4; j++) {
                    int col = nb + j * 8 + 2 * t;
                    float2 v; v.x = acc[mt][j][half * 2]; v.y = acc[mt][j][half * 2 + 1];
                    *(float2*)(hp + col) = v;
                }
            }
        }
}

// ======== edge kernel: bf16 mma + ldmatrix, double-buffered meta ========
__global__ __launch_bounds__(512, 2) void edge_bf16_kernel(
        const float* __restrict__ W1, const float* __restrict__ b1,
        const float* __restrict__ W2, const float* __restrict__ b2,
        const int* __restrict__ ei) {
    extern __shared__ char smem[];
    float* cs  = (float*)(smem + ECS);
    int*   ss  = (int*)(smem + ESS);
    int*   ts  = (int*)(smem + ETS);
    float* b1v = (float*)(smem + EB1V);
    float* b2v = (float*)(smem + EB2V);
    const uint32_t sb = smem_u32(smem);

    const int tid = threadIdx.x;
    const int wid = tid >> 5, lane = tid & 31;
    const int g = lane >> 2, t = lane & 3;
    const int mb = (wid & 3) * 32, nb = (wid >> 2) * 32;

    for (int i = tid; i < EK1 * 64; i += 512) {
        int k = i >> 6, n = (i & 63) * 2;
        float lo = (k < R) ? W1[k * H + n] : 0.0f;
        float hi = (k < R) ? W1[k * H + n + 1] : 0.0f;
        uint32_t p; PACK_BF16X2(p, lo, hi);
        *(uint32_t*)(smem + EB1 + (k * EBS + n) * 2) = p;
    }
    for (int i = tid; i < 128 * 64; i += 512) {
        int k = i >> 6, n = (i & 63) * 2;
        uint32_t p; PACK_BF16X2(p, W2[k * H + n], W2[k * H + n + 1]);
        *(uint32_t*)(smem + EB2 + (k * EBS + n) * 2) = p;
    }
    if (tid < 128) { b1v[tid] = b1[tid]; b2v[tid] = b2[tid]; }
    __syncthreads();

    const int lrow = lane & 15;
    const int lk8 = (lane >> 4) << 3;
    uint32_t aA1[2], aA2[2], aB1[2], aB2[2];
#pragma unroll
    for (int mt = 0; mt < 2; mt++) {
        aA1[mt] = sb + EA1  + ((mb + mt * 16 + lrow) * EA1S + lk8) * 2;
        aA2[mt] = sb + EA2_ + ((mb + mt * 16 + lrow) * EA2S + lk8) * 2;
    }
#pragma unroll
    for (int jp = 0; jp < 2; jp++) {
        aB1[jp] = sb + EB1 + (lrow * EBS + nb + jp * 16 + lk8) * 2;
        aB2[jp] = sb + EB2 + (lrow * EBS + nb + jp * 16 + lk8) * 2;
    }

    const float delta = CUTOFF / (float)(R - 1);
    const float coeff = -0.5f / (delta * delta);

    int buf = 0;
    for (int tile = blockIdx.x; tile < N_ETC; tile += gridDim.x, buf ^= 1) {
        int e0 = tile * ETILE;
        if (tid < 128) {
            cs[buf * 128 + tid] = g_C[e0 + tid];
            ss[buf * 128 + tid] = ei[e0 + tid];
            ts[buf * 128 + tid] = ei[N_EDGES + e0 + tid];
        }
        {
            int e = tid >> 2;
            int k0 = (tid & 3) * 16;
            float dv = g_d[e0 + e];
#pragma unroll
            for (int kp = 0; kp < 8; kp++) {
                int k = k0 + 2 * kp;
                float v0 = 0.f, v1 = 0.f;
                if (k < R)     { float u = dv - (float)k * delta;       v0 = __expf(coeff * u * u); }
                if (k + 1 < R) { float u = dv - (float)(k + 1) * delta; v1 = __expf(coeff * u * u); }
                uint32_t p; PACK_BF16X2(p, v0, v1);
                *(uint32_t*)(smem + EA1 + (e * EA1S + k) * 2) = p;
            }
        }
        __syncthreads();   // sync1

        float acc[2][4][4];
        bf16_gemm<4>(aA1[0], aA1[1], aB1[0], aB1[1], 16 * EBS * 2, b1v, nb, t, acc);
#pragma unroll
        for (int mt = 0; mt < 2; mt++) {
            int r2 = mb + mt * 16 + g;
#pragma unroll
            for (int j = 0; j < 4; j++) {
                int col = nb + j * 8 + 2 * t;
                uint32_t p0, p1;
                PACK_BF16X2(p0, ftanh(acc[mt][j][0]), ftanh(acc[mt][j][1]));
                PACK_BF16X2(p1, ftanh(acc[mt][j][2]), ftanh(acc[mt][j][3]));
                *(uint32_t*)(smem + EA2_ + (r2 * EA2S + col) * 2) = p0;
                *(uint32_t*)(smem + EA2_ + ((r2 + 8) * EA2S + col) * 2) = p1;
            }
        }
        __syncthreads();   // sync2

        bf16_gemm<8>(aA2[0], aA2[1], aB2[0], aB2[1], 16 * EBS * 2, b2v, nb, t, acc);

#pragma unroll
        for (int mt = 0; mt < 2; mt++)
#pragma unroll
            for (int half = 0; half < 2; half++) {
                int row = mb + mt * 16 + half * 8 + g;
                float c = cs[buf * 128 + row];
                if (c != 0.0f) {
                    const float* hp = g_h + (size_t)ss[buf * 128 + row] * H + nb;
                    float* ap = g_agg + (size_t)ts[buf * 128 + row] * H + nb;
#pragma unroll
                    for (int j = 0; j < 4; j++) {
                        int o = j * 8 + 2 * t;
                        float2 h2 = *(const float2*)(hp + o);
                        REDV2(ap + o, acc[mt][j][half * 2 + 0] * c * h2.x,
                                      acc[mt][j][half * 2 + 1] * c * h2.y);
                    }
                }
            }
    }
}

// ---- update (bf16): x += tanh(agg@lin2+b1)@blk + b2; then fused lin1 OR out head ----
__global__ __launch_bounds__(512) void update_bf16(
        const float* __restrict__ lin2_w, const float* __restrict__ lin2_b,
        const float* __restrict__ blk_w, const float* __restrict__ blk_b,
        const float* __restrict__ lin1n_w,
        const float* __restrict__ ow1, const float* __restrict__ ob1,
        const float* __restrict__ ow2, const float* __restrict__ ob2v,
        const int* __restrict__ batch, float* __restrict__ outp) {
    extern __shared__ char smem[];
    float* b1v = (float*)(smem + NB1V);
    float* b2v = (float*)(smem + NB2V);
    float* b3v = (float*)(smem + NB3V);
    float* w2s = (float*)(smem + NW2V);
    const uint32_t sb = smem_u32(smem);
    const int tid = threadIdx.x;
    const int wid = tid >> 5, lane = tid & 31;
    const int g = lane >> 2, t = lane & 3;
    const int mb = (wid & 3) * 32, nb = (wid >> 2) * 32;
    const int lrow = lane & 15, lk8 = (lane >> 4) << 3;
    const bool has_lin1 = (lin1n_w != nullptr);

    fill_wbf16(smem, NW1, lin2_w, tid);
    fill_wbf16(smem, NW2, blk_w, tid);
    if (has_lin1) {
        fill_wbf16(smem, NW3, lin1n_w, tid);
        if (tid < 128) { b3v[tid] = 0.0f; w2s[tid] = 0.0f; }
    } else {
        // out-head W3: [128k][128n], cols 0..63 = out_w1, 64..127 = 0
        for (int i = tid; i < 128 * 64; i += 512) {
            int k = i >> 6, n = (i & 63) * 2;
            float lo = (n < 64)     ? ow1[k * 64 + n]     : 0.0f;
            float hi = (n + 1 < 64) ? ow1[k * 64 + n + 1] : 0.0f;
            uint32_t p; PACK_BF16X2(p, lo, hi);
            *(uint32_t*)(smem + NW3 + (k * NBS + n) * 2) = p;
        }
        if (tid < 128) {
            b3v[tid] = (tid < 64) ? ob1[tid] : 0.0f;
            w2s[tid] = (tid < 64) ? ow2[tid] : 0.0f;
        }
    }
    if (tid < 128) { b1v[tid] = lin2_b[tid]; b2v[tid] = blk_b[tid]; }
    int a0 = blockIdx.x * TILE_A;
    fill_abf16(smem, NA, g_agg, a0, tid);
    __syncthreads();

    for (int i = tid; i < TILE_A * 32; i += 512) {
        int r = i >> 5, c = i & 31;
        if (a0 + r < N_ATOMS) {
            float4 z; z.x = z.y = z.z = z.w = 0.f;
            ((float4*)g_agg)[(size_t)(a0 + r) * 32 + c] = z;
        }
    }

    uint32_t aA0 = sb + NA + ((mb + lrow) * NBS + lk8) * 2;
    uint32_t aA1 = sb + NA + ((mb + 16 + lrow) * NBS + lk8) * 2;
    uint32_t aW1_0 = sb + NW1 + (lrow * NBS + nb + lk8) * 2;
    uint32_t aW1_1 = sb + NW1 + (lrow * NBS + nb + 16 + lk8) * 2;
    uint32_t aW2_0 = sb + NW2 + (lrow * NBS + nb + lk8) * 2;
    uint32_t aW2_1 = sb + NW2 + (lrow * NBS + nb + 16 + lk8) * 2;
    uint32_t aW3_0 = sb + NW3 + (lrow * NBS + nb + lk8) * 2;
    uint32_t aW3_1 = sb + NW3 + (lrow * NBS + nb + 16 + lk8) * 2;
    const int bstep = 16 * NBS * 2;

    float acc[2][4][4];
    bf16_gemm<8>(aA0, aA1, aW1_0, aW1_1, bstep, b1v, nb, t, acc);
    __syncthreads();
#pragma unroll
    for (int mt = 0; mt < 2; mt++) {
        int r = mb + mt * 16 + g;
#pragma unroll
        for (int j = 0; j < 4; j++) {
            int col = nb + j * 8 + 2 * t;
            uint32_t p0, p1;
            PACK_BF16X2(p0, ftanh(acc[mt][j][0]), ftanh(acc[mt][j][1]));
            PACK_BF16X2(p1, ftanh(acc[mt][j][2]), ftanh(acc[mt][j][3]));
            *(uint32_t*)(smem + NA + (r * NBS + col) * 2) = p0;
            *(uint32_t*)(smem + NA + ((r + 8) * NBS + col) * 2) = p1;
        }
    }
    __syncthreads();

    bf16_gemm<8>(aA0, aA1, aW2_0, aW2_1, bstep, b2v, nb, t, acc);
    __syncthreads();

    // x_new = x + acc; write fp32 x (lin1 mode only); stage bf16(x_new) into A
#pragma unroll
    for (int mt = 0; mt < 2; mt++)
#pragma unroll
        for (int half = 0; half < 2; half++) {
            int row = mb + mt * 16 + half * 8 + g;
            bool valid = (a0 + row < N_ATOMS);
            float* xp = valid ? g_x + (size_t)(a0 + row) * H : nullptr;
#pragma unroll
            for (int j = 0; j < 4; j++) {
                int col = nb + j * 8 + 2 * t;
                float nx = 0.f, ny = 0.f;
                if (valid) {
                    float2 xv = *(const float2*)(xp + col);
                    nx = xv.x + acc[mt][j][half * 2 + 0];
                    ny = xv.y + acc[mt][j][half * 2 + 1];
                    if (has_lin1) {
                        float2 o; o.x = nx; o.y = ny;
                        *(float2*)(xp + col) = o;
                    }
                }
                uint32_t p; PACK_BF16X2(p, nx, ny);
                *(uint32_t*)(smem + NA + (row * NBS + col) * 2) = p;
            }
        }
    __syncthreads();

    // GEMM3: x_new @ (lin1_next | out_w1_padded) + b3
    bf16_gemm<8>(aA0, aA1, aW3_0, aW3_1, bstep, b3v, nb, t, acc);

    if (has_lin1) {
#pragma unroll
        for (int mt = 0; mt < 2; mt++)
#pragma unroll
            for (int half = 0; half < 2; half++) {
                int row = mb + mt * 16 + half * 8 + g;
                if (a0 + row < N_ATOMS) {
                    float* hp = g_h + (size_t)(a0 + row) * H;
#pragma unroll
                    for (int j = 0; j < 4; j++) {
                        int col = nb + j * 8 + 2 * t;
                        float2 v; v.x = acc[mt][j][half * 2]; v.y = acc[mt][j][half * 2 + 1];
                        *(float2*)(hp + col) = v;
                    }
                }
            }
    } else {
        // output head: e = tanh(acc) @ out_w2 + out_b2; scatter per molecule
        float ob2 = ob2v[0];
#pragma unroll
        for (int mt = 0; mt < 2; mt++)
#pragma unroll
            for (int half = 0; half < 2; half++) {
                int row = mb + mt * 16 + half * 8 + g;
                float s = 0.f;
#pragma unroll
                for (int j = 0; j < 4; j++) {
                    int c0 = nb + j * 8 + 2 * t;
                    s += ftanh(acc[mt][j][half * 2 + 0]) * w2s[c0];
                    s += ftanh(acc[mt][j][half * 2 + 1]) * w2s[c0 + 1];
                }
                s += __shfl_xor_sync(0xffffffffu, s, 1);
                s += __shfl_xor_sync(0xffffffffu, s, 2);
                int a = a0 + row;
                if (t == 0 && nb < 64 && a < N_ATOMS) {
                    float add = s + ((nb == 0) ? ob2 : 0.0f);
                    atomicAdd(&outp[batch[a]], add);
                }
            }
    }
}

// ---------------- output zero ----------------
__global__ void zero_out_kernel(float* out) {
    if (threadIdx.x < NEX) out[threadIdx.x] = 0.0f;
}

// ---------------- host launcher ----------------
extern "C" void kernel_launch(void* const* d_in, const int* in_sizes, int n_in,
                              void* d_out, int out_size) {
    const float* pos        = (const float*)d_in[0];
    const int*   atom_types = (const int*)  d_in[1];
    const int*   edge_index = (const int*)  d_in[2];
    const int*   batch      = (const int*)  d_in[3];
    const float* embedding  = (const float*)d_in[4];
    const float* filt_w1    = (const float*)d_in[5];
    const float* filt_b1    = (const float*)d_in[6];
    const float* filt_w2    = (const float*)d_in[7];
    const float* filt_b2    = (const float*)d_in[8];
    const float* lin1_w     = (const float*)d_in[9];
    const float* lin2_w     = (const float*)d_in[10];
    const float* lin2_b     = (const float*)d_in[11];
    const float* blk_w      = (const float*)d_in[12];
    const float* blk_b      = (const float*)d_in[13];
    const float* out_w1     = (const float*)d_in[14];
    const float* out_b1     = (const float*)d_in[15];
    const float* out_w2     = (const float*)d_in[16];
    const float* out_b2     = (const float*)d_in[17];
    float* out = (float*)d_out;

    cudaFuncSetAttribute(edge_bf16_kernel, cudaFuncAttributeMaxDynamicSharedMemorySize, SMB_EDGE);
    cudaFuncSetAttribute(lin1_bf16,        cudaFuncAttributeMaxDynamicSharedMemorySize, SMB_LIN1);
    cudaFuncSetAttribute(update_bf16,      cudaFuncAttributeMaxDynamicSharedMemorySize, SMB_UPD);

    geom_kernel<<<(N_EDGES + 255) / 256, 256>>>(pos, edge_index);
    lin1_bf16<<<N_ATILES, 512, SMB_LIN1>>>(atom_types, embedding, lin1_w);

    for (int b = 0; b < NB; b++) {
        edge_bf16_kernel<<<296, 512, SMB_EDGE>>>(filt_w1 + b * R * H, filt_b1 + b * H,
                                                 filt_w2 + b * H * H, filt_b2 + b * H,
                                                 edge_index);
        if (b + 1 < NB) {
            update_bf16<<<N_ATILES, 512, SMB_UPD>>>(lin2_w + b * H * H, lin2_b + b * H,
                                                    blk_w + b * H * H, blk_b + b * H,
                                                    lin1_w + (b + 1) * H * H,
                                                    nullptr, nullptr, nullptr, nullptr,
                                                    nullptr, nullptr);
        } else {
            zero_out_kernel<<<1, 64>>>(out);
            update_bf16<<<N_ATILES, 512, SMB_UPD>>>(lin2_w + b * H * H, lin2_b + b * H,
                                                    blk_w + b * H * H, blk_b + b * H,
                                                    nullptr,
                                                    out_w1, out_b1, out_w2, out_b2,
                                                    batch, out);
        }
    }
}

// round 16
// speedup vs baseline: 1.0708x; 1.0708x over previous
#include <cuda_runtime.h>
#include <math.h>
#include <stdint.h>

#define N_ATOMS 30000
#define N_EDGES 480000
#define H 128
#define R 50
#define NB 3
#define NEX 64
#define CUTOFF 10.0f
#define PI_F 3.14159265358979323846f

#define TILE_A 128
#define N_ATILES ((N_ATOMS + TILE_A - 1) / TILE_A)  // 235

// ---- bf16 edge kernel constants ----
#define ETILE 128
#define N_ETC (N_EDGES / ETILE)   // 3750
#define EK1 64
#define EBS 136
#define EA1S 72
#define EA2S 136
#define EB1  0
#define EB2  (EB1 + EK1 * EBS * 2)        // 17408
#define EA1  (EB2 + 128 * EBS * 2)        // 52224
#define EA2_ (EA1 + 128 * EA1S * 2)       // 70656
#define ECS  (EA2_ + 128 * EA2S * 2)      // 105472 (2x512B double-buffered)
#define ESS  (ECS + 1024)
#define ETS  (ESS + 1024)
#define EB1V (ETS + 1024)
#define EB2V (EB1V + 512)
#define SMB_EDGE (EB2V + 512)             // 109568 B -> 2 CTAs/SM

// ---- bf16 node kernel constants (2 CTA/SM layout: W3 folded into W1) ----
#define NBS 136
#define NW1 0
#define NW2 (NW1 + 128 * NBS * 2)         // 34816
#define NA  (NW2 + 128 * NBS * 2)         // 69632
#define NB1V (NA + 128 * NBS * 2)         // 104448
#define NB2V (NB1V + 512)
#define NZB  (NB2V + 512)
#define SMB_UPD (NZB + 512)               // 105984 B -> 2 CTAs/SM
#define LW  0
#define LA  (LW + 128 * NBS * 2)
#define LZB (LA + 128 * NBS * 2)
#define SMB_LIN1 (LZB + 512)

#define REDV2(p, a, b) \
    asm volatile("red.global.add.v2.f32 [%0], {%1,%2};" \
                 :: "l"(p), "f"(a), "f"(b) : "memory")
#define MMA_BF16(acc, a, b0, b1) \
    asm volatile("mma.sync.aligned.m16n8k16.row.col.f32.bf16.bf16.f32 " \
                 "{%0,%1,%2,%3},{%4,%5,%6,%7},{%8,%9},{%0,%1,%2,%3};" \
                 : "+f"((acc)[0]), "+f"((acc)[1]), "+f"((acc)[2]), "+f"((acc)[3]) \
                 : "r"((a)[0]), "r"((a)[1]), "r"((a)[2]), "r"((a)[3]), "r"(b0), "r"(b1))
#define LDMX4(r, addr) \
    asm volatile("ldmatrix.sync.aligned.m8n8.x4.shared.b16 {%0,%1,%2,%3}, [%4];" \
                 : "=r"((r)[0]), "=r"((r)[1]), "=r"((r)[2]), "=r"((r)[3]) : "r"(addr))
#define LDMX4T(r, addr) \
    asm volatile("ldmatrix.sync.aligned.m8n8.x4.trans.shared.b16 {%0,%1,%2,%3}, [%4];" \
                 : "=r"((r)[0]), "=r"((r)[1]), "=r"((r)[2]), "=r"((r)[3]) : "r"(addr))
#define PACK_BF16X2(res, lo, hi) \
    asm("cvt.rn.satfinite.bf16x2.f32 %0, %1, %2;" : "=r"(res) : "f"(hi), "f"(lo))

__device__ __forceinline__ float ftanh(float x) {
    float e = __expf(2.0f * x);
    return fmaf(-2.0f, __frcp_rn(e + 1.0f), 1.0f);
}
__device__ __forceinline__ uint32_t smem_u32(const void* p) {
    uint32_t a;
    asm("{ .reg .u64 t; cvta.to.shared.u64 t, %1; cvt.u32.u64 %0, t; }" : "=r"(a) : "l"(p));
    return a;
}

// ---------------- device scratch (allocation-free) ----------------
__device__ float g_d[N_EDGES];
__device__ float g_C[N_EDGES];
__device__ float g_x[N_ATOMS * H];
__device__ float g_h[N_ATOMS * H];
__device__ float g_agg[N_ATOMS * H];

// ---- shared bf16 GEMM mainloop ----
template <int KSTEPS>
__device__ __forceinline__ void bf16_gemm(uint32_t aA0, uint32_t aA1,
                                          uint32_t aB0, uint32_t aB1, int bstep,
                                          const float* bias, int nb, int t,
                                          float acc[2][4][4]) {
#pragma unroll
    for (int mt = 0; mt < 2; mt++)
#pragma unroll
        for (int j = 0; j < 4; j++) {
            int c0 = nb + j * 8 + 2 * t;
            acc[mt][j][0] = bias[c0]; acc[mt][j][1] = bias[c0 + 1];
            acc[mt][j][2] = bias[c0]; acc[mt][j][3] = bias[c0 + 1];
        }
#pragma unroll
    for (int ks = 0; ks < KSTEPS; ks++) {
        uint32_t a0[4], a1[4], f0[4], f1[4];
        LDMX4(a0, aA0 + ks * 32);
        LDMX4(a1, aA1 + ks * 32);
        LDMX4T(f0, aB0 + ks * bstep);
        LDMX4T(f1, aB1 + ks * bstep);
        MMA_BF16(acc[0][0], a0, f0[0], f0[1]);
        MMA_BF16(acc[0][1], a0, f0[2], f0[3]);
        MMA_BF16(acc[0][2], a0, f1[0], f1[1]);
        MMA_BF16(acc[0][3], a0, f1[2], f1[3]);
        MMA_BF16(acc[1][0], a1, f0[0], f0[1]);
        MMA_BF16(acc[1][1], a1, f0[2], f0[3]);
        MMA_BF16(acc[1][2], a1, f1[0], f1[1]);
        MMA_BF16(acc[1][3], a1, f1[2], f1[3]);
    }
}

__device__ __forceinline__ void fill_wbf16(char* smem, int off,
                                           const float* __restrict__ W, int tid) {
    for (int i = tid; i < 128 * 64; i += 512) {
        int k = i >> 6, n = (i & 63) * 2;
        uint32_t p; PACK_BF16X2(p, W[k * H + n], W[k * H + n + 1]);
        *(uint32_t*)(smem + off + (k * NBS + n) * 2) = p;
    }
}

__device__ __forceinline__ void fill_abf16(char* smem, int off,
                                           const float* __restrict__ src,
                                           int a0, int tid) {
    for (int i = tid; i < 128 * 64; i += 512) {
        int r = i >> 6, n = (i & 63) * 2;
        int a = a0 + r;
        float lo = 0.f, hi = 0.f;
        if (a < N_ATOMS) { lo = src[(size_t)a * H + n]; hi = src[(size_t)a * H + n + 1]; }
        uint32_t p; PACK_BF16X2(p, lo, hi);
        *(uint32_t*)(smem + off + (r * NBS + n) * 2) = p;
    }
}

// ---------------- geometry: distances + cutoff ----------------
__global__ void geom_kernel(const float* __restrict__ pos,
                            const int* __restrict__ ei) {
    int e = blockIdx.x * blockDim.x + threadIdx.x;
    if (e >= N_EDGES) return;
    int s = ei[e];
    int t = ei[N_EDGES + e];
    float dx = pos[3 * s + 0] - pos[3 * t + 0];
    float dy = pos[3 * s + 1] - pos[3 * t + 1];
    float dz = pos[3 * s + 2] - pos[3 * t + 2];
    float d = sqrtf(dx * dx + dy * dy + dz * dz + 1e-12f);
    g_d[e] = d;
    g_C[e] = (d < CUTOFF) ? 0.5f * (cosf(d * PI_F / CUTOFF) + 1.0f) : 0.0f;
}

// ------- lin1 + fused embedding gather + agg zero (block 0 only) -------
__global__ __launch_bounds__(512) void lin1_bf16(const int* __restrict__ types,
                                                 const float* __restrict__ emb,
                                                 const float* __restrict__ W) {
    extern __shared__ char smem[];
    float* zb = (float*)(smem + LZB);
    const uint32_t sb = smem_u32(smem);
    const int tid = threadIdx.x;
    const int wid = tid >> 5, lane = tid & 31;
    const int g = lane >> 2, t = lane & 3;
    const int mb = (wid & 3) * 32, nb = (wid >> 2) * 32;
    const int lrow = lane & 15, lk8 = (lane >> 4) << 3;

    fill_wbf16(smem, LW, W, tid);
    if (tid < 128) zb[tid] = 0.0f;
    int a0 = blockIdx.x * TILE_A;
    for (int i = tid; i < 128 * 64; i += 512) {
        int r = i >> 6, n = (i & 63) * 2;
        int a = a0 + r;
        float lo = 0.f, hi = 0.f;
        if (a < N_ATOMS) {
            int ty = types[a];
            lo = emb[(size_t)ty * H + n]; hi = emb[(size_t)ty * H + n + 1];
            float2 w; w.x = lo; w.y = hi;
            *(float2*)(g_x + (size_t)a * H + n) = w;
        }
        uint32_t p; PACK_BF16X2(p, lo, hi);
        *(uint32_t*)(smem + LA + (r * NBS + n) * 2) = p;
    }
    for (int i = tid; i < TILE_A * 32; i += 512) {
        int r = i >> 5, c = i & 31;
        if (a0 + r < N_ATOMS) {
            float4 z; z.x = z.y = z.z = z.w = 0.f;
            ((float4*)g_agg)[(size_t)(a0 + r) * 32 + c] = z;
        }
    }
    __syncthreads();

    uint32_t aA0 = sb + LA + ((mb + lrow) * NBS + lk8) * 2;
    uint32_t aA1 = sb + LA + ((mb + 16 + lrow) * NBS + lk8) * 2;
    uint32_t aB0 = sb + LW + (lrow * NBS + nb + lk8) * 2;
    uint32_t aB1 = sb + LW + (lrow * NBS + nb + 16 + lk8) * 2;

    float acc[2][4][4];
    bf16_gemm<8>(aA0, aA1, aB0, aB1, 16 * NBS * 2, zb, nb, t, acc);

#pragma unroll
    for (int mt = 0; mt < 2; mt++)
#pragma unroll
        for (int half = 0; half < 2; half++) {
            int row = mb + mt * 16 + half * 8 + g;
            if (a0 + row < N_ATOMS) {
                float* hp = g_h + (size_t)(a0 + row) * H;
#pragma unroll
                for (int j = 0; j < 4; j++) {
                    int col = nb + j * 8 + 2 * t;
                    float2 v; v.x = acc[mt][j][half * 2]; v.y = acc[mt][j][half * 2 + 1];
                    *(float2*)(hp + col) = v;
                }
            }
        }
}

// ======== edge kernel: bf16 mma + ldmatrix, double-buffered meta ========
__global__ __launch_bounds__(512, 2) void edge_bf16_kernel(
        const float* __restrict__ W1, const float* __restrict__ b1,
        const float* __restrict__ W2, const float* __restrict__ b2,
        const int* __restrict__ ei) {
    extern __shared__ char smem[];
    float* cs  = (float*)(smem + ECS);
    int*   ss  = (int*)(smem + ESS);
    int*   ts  = (int*)(smem + ETS);
    float* b1v = (float*)(smem + EB1V);
    float* b2v = (float*)(smem + EB2V);
    const uint32_t sb = smem_u32(smem);

    const int tid = threadIdx.x;
    const int wid = tid >> 5, lane = tid & 31;
    const int g = lane >> 2, t = lane & 3;
    const int mb = (wid & 3) * 32, nb = (wid >> 2) * 32;

    for (int i = tid; i < EK1 * 64; i += 512) {
        int k = i >> 6, n = (i & 63) * 2;
        float lo = (k < R) ? W1[k * H + n] : 0.0f;
        float hi = (k < R) ? W1[k * H + n + 1] : 0.0f;
        uint32_t p; PACK_BF16X2(p, lo, hi);
        *(uint32_t*)(smem + EB1 + (k * EBS + n) * 2) = p;
    }
    for (int i = tid; i < 128 * 64; i += 512) {
        int k = i >> 6, n = (i & 63) * 2;
        uint32_t p; PACK_BF16X2(p, W2[k * H + n], W2[k * H + n + 1]);
        *(uint32_t*)(smem + EB2 + (k * EBS + n) * 2) = p;
    }
    if (tid < 128) { b1v[tid] = b1[tid]; b2v[tid] = b2[tid]; }
    __syncthreads();

    const int lrow = lane & 15;
    const int lk8 = (lane >> 4) << 3;
    uint32_t aA1[2], aA2[2], aB1[2], aB2[2];
#pragma unroll
    for (int mt = 0; mt < 2; mt++) {
        aA1[mt] = sb + EA1  + ((mb + mt * 16 + lrow) * EA1S + lk8) * 2;
        aA2[mt] = sb + EA2_ + ((mb + mt * 16 + lrow) * EA2S + lk8) * 2;
    }
#pragma unroll
    for (int jp = 0; jp < 2; jp++) {
        aB1[jp] = sb + EB1 + (lrow * EBS + nb + jp * 16 + lk8) * 2;
        aB2[jp] = sb + EB2 + (lrow * EBS + nb + jp * 16 + lk8) * 2;
    }

    const float delta = CUTOFF / (float)(R - 1);
    const float coeff = -0.5f / (delta * delta);

    int buf = 0;
    for (int tile = blockIdx.x; tile < N_ETC; tile += gridDim.x, buf ^= 1) {
        int e0 = tile * ETILE;
        if (tid < 128) {
            cs[buf * 128 + tid] = g_C[e0 + tid];
            ss[buf * 128 + tid] = ei[e0 + tid];
            ts[buf * 128 + tid] = ei[N_EDGES + e0 + tid];
        }
        {
            int e = tid >> 2;
            int k0 = (tid & 3) * 16;
            float dv = g_d[e0 + e];
#pragma unroll
            for (int kp = 0; kp < 8; kp++) {
                int k = k0 + 2 * kp;
                float v0 = 0.f, v1 = 0.f;
                if (k < R)     { float u = dv - (float)k * delta;       v0 = __expf(coeff * u * u); }
                if (k + 1 < R) { float u = dv - (float)(k + 1) * delta; v1 = __expf(coeff * u * u); }
                uint32_t p; PACK_BF16X2(p, v0, v1);
                *(uint32_t*)(smem + EA1 + (e * EA1S + k) * 2) = p;
            }
        }
        __syncthreads();   // sync1

        float acc[2][4][4];
        bf16_gemm<4>(aA1[0], aA1[1], aB1[0], aB1[1], 16 * EBS * 2, b1v, nb, t, acc);
#pragma unroll
        for (int mt = 0; mt < 2; mt++) {
            int r2 = mb + mt * 16 + g;
#pragma unroll
            for (int j = 0; j < 4; j++) {
                int col = nb + j * 8 + 2 * t;
                uint32_t p0, p1;
                PACK_BF16X2(p0, ftanh(acc[mt][j][0]), ftanh(acc[mt][j][1]));
                PACK_BF16X2(p1, ftanh(acc[mt][j][2]), ftanh(acc[mt][j][3]));
                *(uint32_t*)(smem + EA2_ + (r2 * EA2S + col) * 2) = p0;
                *(uint32_t*)(smem + EA2_ + ((r2 + 8) * EA2S + col) * 2) = p1;
            }
        }
        __syncthreads();   // sync2

        bf16_gemm<8>(aA2[0], aA2[1], aB2[0], aB2[1], 16 * EBS * 2, b2v, nb, t, acc);

#pragma unroll
        for (int mt = 0; mt < 2; mt++)
#pragma unroll
            for (int half = 0; half < 2; half++) {
                int row = mb + mt * 16 + half * 8 + g;
                float c = cs[buf * 128 + row];
                if (c != 0.0f) {
                    const float* hp = g_h + (size_t)ss[buf * 128 + row] * H + nb;
                    float* ap = g_agg + (size_t)ts[buf * 128 + row] * H + nb;
#pragma unroll
                    for (int j = 0; j < 4; j++) {
                        int o = j * 8 + 2 * t;
                        float2 h2 = *(const float2*)(hp + o);
                        REDV2(ap + o, acc[mt][j][half * 2 + 0] * c * h2.x,
                                      acc[mt][j][half * 2 + 1] * c * h2.y);
                    }
                }
            }
    }
}

// ---- update (bf16, 2 CTA/SM): x += tanh(agg@lin2+b1)@blk + b2 [+ fused lin1] ----
// W3 (lin1_next) reuses the lin2 weight buffer after GEMM1 completes.
__global__ __launch_bounds__(512, 2) void update_bf16(
        const float* __restrict__ lin2_w, const float* __restrict__ lin2_b,
        const float* __restrict__ blk_w, const float* __restrict__ blk_b,
        const float* __restrict__ lin1n_w) {
    extern __shared__ char smem[];
    float* b1v = (float*)(smem + NB1V);
    float* b2v = (float*)(smem + NB2V);
    float* zb  = (float*)(smem + NZB);
    const uint32_t sb = smem_u32(smem);
    const int tid = threadIdx.x;
    const int wid = tid >> 5, lane = tid & 31;
    const int g = lane >> 2, t = lane & 3;
    const int mb = (wid & 3) * 32, nb = (wid >> 2) * 32;
    const int lrow = lane & 15, lk8 = (lane >> 4) << 3;
    const bool has_lin1 = (lin1n_w != nullptr);

    fill_wbf16(smem, NW1, lin2_w, tid);
    fill_wbf16(smem, NW2, blk_w, tid);
    if (tid < 128) { b1v[tid] = lin2_b[tid]; b2v[tid] = blk_b[tid]; zb[tid] = 0.0f; }
    int a0 = blockIdx.x * TILE_A;
    fill_abf16(smem, NA, g_agg, a0, tid);
    __syncthreads();

    for (int i = tid; i < TILE_A * 32; i += 512) {
        int r = i >> 5, c = i & 31;
        if (a0 + r < N_ATOMS) {
            float4 z; z.x = z.y = z.z = z.w = 0.f;
            ((float4*)g_agg)[(size_t)(a0 + r) * 32 + c] = z;
        }
    }

    uint32_t aA0 = sb + NA + ((mb + lrow) * NBS + lk8) * 2;
    uint32_t aA1 = sb + NA + ((mb + 16 + lrow) * NBS + lk8) * 2;
    uint32_t aW1_0 = sb + NW1 + (lrow * NBS + nb + lk8) * 2;
    uint32_t aW1_1 = sb + NW1 + (lrow * NBS + nb + 16 + lk8) * 2;
    uint32_t aW2_0 = sb + NW2 + (lrow * NBS + nb + lk8) * 2;
    uint32_t aW2_1 = sb + NW2 + (lrow * NBS + nb + 16 + lk8) * 2;
    const int bstep = 16 * NBS * 2;

    float acc[2][4][4];
    // GEMM1: agg @ lin2 + b1 (reads NW1 = lin2)
    bf16_gemm<8>(aA0, aA1, aW1_0, aW1_1, bstep, b1v, nb, t, acc);
    __syncthreads();   // all GEMM1 reads of NW1 and NA done

    // tanh -> NA; concurrently overwrite NW1 with lin1_next (disjoint regions)
#pragma unroll
    for (int mt = 0; mt < 2; mt++) {
        int r = mb + mt * 16 + g;
#pragma unroll
        for (int j = 0; j < 4; j++) {
            int col = nb + j * 8 + 2 * t;
            uint32_t p0, p1;
            PACK_BF16X2(p0, ftanh(acc[mt][j][0]), ftanh(acc[mt][j][1]));
            PACK_BF16X2(p1, ftanh(acc[mt][j][2]), ftanh(acc[mt][j][3]));
            *(uint32_t*)(smem + NA + (r * NBS + col) * 2) = p0;
            *(uint32_t*)(smem + NA + ((r + 8) * NBS + col) * 2) = p1;
        }
    }
    if (has_lin1) fill_wbf16(smem, NW1, lin1n_w, tid);
    __syncthreads();

    // GEMM2: t @ blk + b2
    bf16_gemm<8>(aA0, aA1, aW2_0, aW2_1, bstep, b2v, nb, t, acc);
    __syncthreads();   // all GEMM2 reads of NA done before overwrite

    // x_new = x + acc; write fp32 x; stage bf16(x_new) into NA for GEMM3
#pragma unroll
    for (int mt = 0; mt < 2; mt++)
#pragma unroll
        for (int half = 0; half < 2; half++) {
            int row = mb + mt * 16 + half * 8 + g;
            bool valid = (a0 + row < N_ATOMS);
            float* xp = valid ? g_x + (size_t)(a0 + row) * H : nullptr;
#pragma unroll
            for (int j = 0; j < 4; j++) {
                int col = nb + j * 8 + 2 * t;
                float nx = 0.f, ny = 0.f;
                if (valid) {
                    float2 xv = *(const float2*)(xp + col);
                    nx = xv.x + acc[mt][j][half * 2 + 0];
                    ny = xv.y + acc[mt][j][half * 2 + 1];
                    float2 o; o.x = nx; o.y = ny;
                    *(float2*)(xp + col) = o;
                }
                if (has_lin1) {
                    uint32_t p; PACK_BF16X2(p, nx, ny);
                    *(uint32_t*)(smem + NA + (row * NBS + col) * 2) = p;
                }
            }
        }

    if (!has_lin1) return;
    __syncthreads();

    // GEMM3: x_new @ lin1_next (NW1) -> g_h
    bf16_gemm<8>(aA0, aA1, aW1_0, aW1_1, bstep, zb, nb, t, acc);
#pragma unroll
    for (int mt = 0; mt < 2; mt++)
#pragma unroll
        for (int half = 0; half < 2; half++) {
            int row = mb + mt * 16 + half * 8 + g;
            if (a0 + row < N_ATOMS) {
                float* hp = g_h + (size_t)(a0 + row) * H;
#pragma unroll
                for (int j = 0; j < 4; j++) {
                    int col = nb + j * 8 + 2 * t;
                    float2 v; v.x = acc[mt][j][half * 2]; v.y = acc[mt][j][half * 2 + 1];
                    *(float2*)(hp + col) = v;
                }
            }
        }
}

// ---------------- output head + per-molecule reduction (fp32) ----------------
__global__ void zero_out_kernel(float* out) {
    if (threadIdx.x < NEX) out[threadIdx.x] = 0.0f;
}

__global__ void out_kernel(const float* __restrict__ w1, const float* __restrict__ b1v,
                           const float* __restrict__ w2, const float* __restrict__ b2v,
                           const int* __restrict__ batch, float* __restrict__ out) {
    __shared__ float w1s[H * 64];
    __shared__ float w2s[64];
    __shared__ float b1s[64];
    __shared__ float xb[8 * H];
    for (int i = threadIdx.x; i < H * 64; i += blockDim.x) w1s[i] = w1[i];
    if (threadIdx.x < 64) { w2s[threadIdx.x] = w2[threadIdx.x]; b1s[threadIdx.x] = b1v[threadIdx.x]; }
    __syncthreads();
    float ob2 = b2v[0];
    int lane = threadIdx.x & 31;
    int w = threadIdx.x >> 5;
    int wpb = blockDim.x >> 5;
    float* rb = xb + w * H;
    for (int a = blockIdx.x * wpb + w; a < N_ATOMS; a += gridDim.x * wpb) {
        float4 xv = ((const float4*)g_x)[a * 32 + lane];
        ((float4*)rb)[lane] = xv;
        __syncwarp();
        float a0 = b1s[lane], a1 = b1s[lane + 32];
#pragma unroll 4
        for (int k = 0; k < H; k++) {
            float xk = rb[k];
            a0 = fmaf(xk, w1s[k * 64 + lane], a0);
            a1 = fmaf(xk, w1s[k * 64 + lane + 32], a1);
        }
        __syncwarp();
        float part = tanhf(a0) * w2s[lane] + tanhf(a1) * w2s[lane + 32];
#pragma unroll
        for (int off = 16; off; off >>= 1)
            part += __shfl_down_sync(0xffffffffu, part, off);
        if (lane == 0) atomicAdd(&out[batch[a]], part + ob2);
    }
}

// ---------------- host launcher ----------------
extern "C" void kernel_launch(void* const* d_in, const int* in_sizes, int n_in,
                              void* d_out, int out_size) {
    const float* pos        = (const float*)d_in[0];
    const int*   atom_types = (const int*)  d_in[1];
    const int*   edge_index = (const int*)  d_in[2];
    const int*   batch      = (const int*)  d_in[3];
    const float* embedding  = (const float*)d_in[4];
    const float* filt_w1    = (const float*)d_in[5];
    const float* filt_b1    = (const float*)d_in[6];
    const float* filt_w2    = (const float*)d_in[7];
    const float* filt_b2    = (const float*)d_in[8];
    const float* lin1_w     = (const float*)d_in[9];
    const float* lin2_w     = (const float*)d_in[10];
    const float* lin2_b     = (const float*)d_in[11];
    const float* blk_w      = (const float*)d_in[12];
    const float* blk_b      = (const float*)d_in[13];
    const float* out_w1     = (const float*)d_in[14];
    const float* out_b1     = (const float*)d_in[15];
    const float* out_w2     = (const float*)d_in[16];
    const float* out_b2     = (const float*)d_in[17];
    float* out = (float*)d_out;

    cudaFuncSetAttribute(edge_bf16_kernel, cudaFuncAttributeMaxDynamicSharedMemorySize, SMB_EDGE);
    cudaFuncSetAttribute(lin1_bf16,        cudaFuncAttributeMaxDynamicSharedMemorySize, SMB_LIN1);
    cudaFuncSetAttribute(update_bf16,      cudaFuncAttributeMaxDynamicSharedMemorySize, SMB_UPD);

    geom_kernel<<<(N_EDGES + 255) / 256, 256>>>(pos, edge_index);
    lin1_bf16<<<N_ATILES, 512, SMB_LIN1>>>(atom_types, embedding, lin1_w);

    for (int b = 0; b < NB; b++) {
        edge_bf16_kernel<<<296, 512, SMB_EDGE>>>(filt_w1 + b * R * H, filt_b1 + b * H,
                                                 filt_w2 + b * H * H, filt_b2 + b * H,
                                                 edge_index);
        const float* lin1n = (b + 1 < NB) ? (lin1_w + (b + 1) * H * H) : nullptr;
        update_bf16<<<N_ATILES, 512, SMB_UPD>>>(lin2_w + b * H * H, lin2_b + b * H,
                                                blk_w + b * H * H, blk_b + b * H,
                                                lin1n);
    }

    zero_out_kernel<<<1, 64>>>(out);
    out_kernel<<<296, 256>>>(out_w1, out_b1, out_w2, out_b2, batch, out);
}

// round 17
// speedup vs baseline: 1.0732x; 1.0022x over previous
#include <cuda_runtime.h>
#include <math.h>
#include <stdint.h>

#define N_ATOMS 30000
#define N_EDGES 480000
#define H 128
#define R 50
#define NB 3
#define NEX 64
#define CUTOFF 10.0f
#define PI_F 3.14159265358979323846f

#define TILE_A 128
#define N_ATILES ((N_ATOMS + TILE_A - 1) / TILE_A)  // 235

// ---- bf16 edge kernel constants ----
#define ETILE 128
#define N_ETC (N_EDGES / ETILE)   // 3750
#define EK1 64
#define EBS 136
#define EA1S 72
#define EA2S 136
#define EB1  0
#define EB2  (EB1 + EK1 * EBS * 2)        // 17408
#define EA1  (EB2 + 128 * EBS * 2)        // 52224
#define EA2_ (EA1 + 128 * EA1S * 2)       // 70656
#define ECS  (EA2_ + 128 * EA2S * 2)      // 105472 (2x512B double-buffered)
#define ESS  (ECS + 1024)
#define ETS  (ESS + 1024)
#define EB1V (ETS + 1024)
#define EB2V (EB1V + 512)
#define SMB_EDGE (EB2V + 512)             // 109568 B -> 2 CTAs/SM

// ---- bf16 node kernel constants (2 CTA/SM) ----
#define NBS 136
#define NW1 0
#define NW2 (NW1 + 128 * NBS * 2)         // 34816
#define NA  (NW2 + 128 * NBS * 2)         // 69632
#define NB1V (NA + 128 * NBS * 2)         // 104448
#define NB2V (NB1V + 512)
#define NZB  (NB2V + 512)
#define SMB_UPD (NZB + 512)               // 105984 B -> 2 CTAs/SM
#define XSTR 132                          // fp32 x-stage row stride (final mode)
#define LW  0
#define LA  (LW + 128 * NBS * 2)
#define LZB (LA + 128 * NBS * 2)
#define SMB_LIN1 (LZB + 512)

#define REDV2(p, a, b) \
    asm volatile("red.global.add.v2.f32 [%0], {%1,%2};" \
                 :: "l"(p), "f"(a), "f"(b) : "memory")
#define MMA_BF16(acc, a, b0, b1) \
    asm volatile("mma.sync.aligned.m16n8k16.row.col.f32.bf16.bf16.f32 " \
                 "{%0,%1,%2,%3},{%4,%5,%6,%7},{%8,%9},{%0,%1,%2,%3};" \
                 : "+f"((acc)[0]), "+f"((acc)[1]), "+f"((acc)[2]), "+f"((acc)[3]) \
                 : "r"((a)[0]), "r"((a)[1]), "r"((a)[2]), "r"((a)[3]), "r"(b0), "r"(b1))
#define LDMX4(r, addr) \
    asm volatile("ldmatrix.sync.aligned.m8n8.x4.shared.b16 {%0,%1,%2,%3}, [%4];" \
                 : "=r"((r)[0]), "=r"((r)[1]), "=r"((r)[2]), "=r"((r)[3]) : "r"(addr))
#define LDMX4T(r, addr) \
    asm volatile("ldmatrix.sync.aligned.m8n8.x4.trans.shared.b16 {%0,%1,%2,%3}, [%4];" \
                 : "=r"((r)[0]), "=r"((r)[1]), "=r"((r)[2]), "=r"((r)[3]) : "r"(addr))
#define PACK_BF16X2(res, lo, hi) \
    asm("cvt.rn.satfinite.bf16x2.f32 %0, %1, %2;" : "=r"(res) : "f"(hi), "f"(lo))

__device__ __forceinline__ float ftanh(float x) {
    float e = __expf(2.0f * x);
    return fmaf(-2.0f, __frcp_rn(e + 1.0f), 1.0f);
}
__device__ __forceinline__ uint32_t smem_u32(const void* p) {
    uint32_t a;
    asm("{ .reg .u64 t; cvta.to.shared.u64 t, %1; cvt.u32.u64 %0, t; }" : "=r"(a) : "l"(p));
    return a;
}

// ---------------- device scratch (allocation-free) ----------------
__device__ float g_d[N_EDGES];
__device__ float g_C[N_EDGES];
__device__ float g_x[N_ATOMS * H];
__device__ float g_h[N_ATOMS * H];
__device__ float g_agg[N_ATOMS * H];

// ---- shared bf16 GEMM mainloop ----
template <int KSTEPS>
__device__ __forceinline__ void bf16_gemm(uint32_t aA0, uint32_t aA1,
                                          uint32_t aB0, uint32_t aB1, int bstep,
                                          const float* bias, int nb, int t,
                                          float acc[2][4][4]) {
#pragma unroll
    for (int mt = 0; mt < 2; mt++)
#pragma unroll
        for (int j = 0; j < 4; j++) {
            int c0 = nb + j * 8 + 2 * t;
            acc[mt][j][0] = bias[c0]; acc[mt][j][1] = bias[c0 + 1];
            acc[mt][j][2] = bias[c0]; acc[mt][j][3] = bias[c0 + 1];
        }
#pragma unroll
    for (int ks = 0; ks < KSTEPS; ks++) {
        uint32_t a0[4], a1[4], f0[4], f1[4];
        LDMX4(a0, aA0 + ks * 32);
        LDMX4(a1, aA1 + ks * 32);
        LDMX4T(f0, aB0 + ks * bstep);
        LDMX4T(f1, aB1 + ks * bstep);
        MMA_BF16(acc[0][0], a0, f0[0], f0[1]);
        MMA_BF16(acc[0][1], a0, f0[2], f0[3]);
        MMA_BF16(acc[0][2], a0, f1[0], f1[1]);
        MMA_BF16(acc[0][3], a0, f1[2], f1[3]);
        MMA_BF16(acc[1][0], a1, f0[0], f0[1]);
        MMA_BF16(acc[1][1], a1, f0[2], f0[3]);
        MMA_BF16(acc[1][2], a1, f1[0], f1[1]);
        MMA_BF16(acc[1][3], a1, f1[2], f1[3]);
    }
}

__device__ __forceinline__ void fill_wbf16(char* smem, int off,
                                           const float* __restrict__ W, int tid) {
    for (int i = tid; i < 128 * 64; i += 512) {
        int k = i >> 6, n = (i & 63) * 2;
        uint32_t p; PACK_BF16X2(p, W[k * H + n], W[k * H + n + 1]);
        *(uint32_t*)(smem + off + (k * NBS + n) * 2) = p;
    }
}

__device__ __forceinline__ void fill_abf16(char* smem, int off,
                                           const float* __restrict__ src,
                                           int a0, int tid) {
    for (int i = tid; i < 128 * 64; i += 512) {
        int r = i >> 6, n = (i & 63) * 2;
        int a = a0 + r;
        float lo = 0.f, hi = 0.f;
        if (a < N_ATOMS) { lo = src[(size_t)a * H + n]; hi = src[(size_t)a * H + n + 1]; }
        uint32_t p; PACK_BF16X2(p, lo, hi);
        *(uint32_t*)(smem + off + (r * NBS + n) * 2) = p;
    }
}

// ---------------- geometry: distances + cutoff ----------------
__global__ void geom_kernel(const float* __restrict__ pos,
                            const int* __restrict__ ei) {
    int e = blockIdx.x * blockDim.x + threadIdx.x;
    if (e >= N_EDGES) return;
    int s = ei[e];
    int t = ei[N_EDGES + e];
    float dx = pos[3 * s + 0] - pos[3 * t + 0];
    float dy = pos[3 * s + 1] - pos[3 * t + 1];
    float dz = pos[3 * s + 2] - pos[3 * t + 2];
    float d = sqrtf(dx * dx + dy * dy + dz * dz + 1e-12f);
    g_d[e] = d;
    g_C[e] = (d < CUTOFF) ? 0.5f * (cosf(d * PI_F / CUTOFF) + 1.0f) : 0.0f;
}

// ------- lin1 + fused embedding gather + agg zero (block 0 only) -------
__global__ __launch_bounds__(512) void lin1_bf16(const int* __restrict__ types,
                                                 const float* __restrict__ emb,
                                                 const float* __restrict__ W) {
    extern __shared__ char smem[];
    float* zb = (float*)(smem + LZB);
    const uint32_t sb = smem_u32(smem);
    const int tid = threadIdx.x;
    const int wid = tid >> 5, lane = tid & 31;
    const int g = lane >> 2, t = lane & 3;
    const int mb = (wid & 3) * 32, nb = (wid >> 2) * 32;
    const int lrow = lane & 15, lk8 = (lane >> 4) << 3;

    fill_wbf16(smem, LW, W, tid);
    if (tid < 128) zb[tid] = 0.0f;
    int a0 = blockIdx.x * TILE_A;
    for (int i = tid; i < 128 * 64; i += 512) {
        int r = i >> 6, n = (i & 63) * 2;
        int a = a0 + r;
        float lo = 0.f, hi = 0.f;
        if (a < N_ATOMS) {
            int ty = types[a];
            lo = emb[(size_t)ty * H + n]; hi = emb[(size_t)ty * H + n + 1];
            float2 w; w.x = lo; w.y = hi;
            *(float2*)(g_x + (size_t)a * H + n) = w;
        }
        uint32_t p; PACK_BF16X2(p, lo, hi);
        *(uint32_t*)(smem + LA + (r * NBS + n) * 2) = p;
    }
    for (int i = tid; i < TILE_A * 32; i += 512) {
        int r = i >> 5, c = i & 31;
        if (a0 + r < N_ATOMS) {
            float4 z; z.x = z.y = z.z = z.w = 0.f;
            ((float4*)g_agg)[(size_t)(a0 + r) * 32 + c] = z;
        }
    }
    __syncthreads();

    uint32_t aA0 = sb + LA + ((mb + lrow) * NBS + lk8) * 2;
    uint32_t aA1 = sb + LA + ((mb + 16 + lrow) * NBS + lk8) * 2;
    uint32_t aB0 = sb + LW + (lrow * NBS + nb + lk8) * 2;
    uint32_t aB1 = sb + LW + (lrow * NBS + nb + 16 + lk8) * 2;

    float acc[2][4][4];
    bf16_gemm<8>(aA0, aA1, aB0, aB1, 16 * NBS * 2, zb, nb, t, acc);

#pragma unroll
    for (int mt = 0; mt < 2; mt++)
#pragma unroll
        for (int half = 0; half < 2; half++) {
            int row = mb + mt * 16 + half * 8 + g;
            if (a0 + row < N_ATOMS) {
                float* hp = g_h + (size_t)(a0 + row) * H;
#pragma unroll
                for (int j = 0; j < 4; j++) {
                    int col = nb + j * 8 + 2 * t;
                    float2 v; v.x = acc[mt][j][half * 2]; v.y = acc[mt][j][half * 2 + 1];
                    *(float2*)(hp + col) = v;
                }
            }
        }
}

// ======== edge kernel: bf16 mma + ldmatrix, double-buffered meta ========
__global__ __launch_bounds__(512, 2) void edge_bf16_kernel(
        const float* __restrict__ W1, const float* __restrict__ b1,
        const float* __restrict__ W2, const float* __restrict__ b2,
        const int* __restrict__ ei) {
    extern __shared__ char smem[];
    float* cs  = (float*)(smem + ECS);
    int*   ss  = (int*)(smem + ESS);
    int*   ts  = (int*)(smem + ETS);
    float* b1v = (float*)(smem + EB1V);
    float* b2v = (float*)(smem + EB2V);
    const uint32_t sb = smem_u32(smem);

    const int tid = threadIdx.x;
    const int wid = tid >> 5, lane = tid & 31;
    const int g = lane >> 2, t = lane & 3;
    const int mb = (wid & 3) * 32, nb = (wid >> 2) * 32;

    for (int i = tid; i < EK1 * 64; i += 512) {
        int k = i >> 6, n = (i & 63) * 2;
        float lo = (k < R) ? W1[k * H + n] : 0.0f;
        float hi = (k < R) ? W1[k * H + n + 1] : 0.0f;
        uint32_t p; PACK_BF16X2(p, lo, hi);
        *(uint32_t*)(smem + EB1 + (k * EBS + n) * 2) = p;
    }
    for (int i = tid; i < 128 * 64; i += 512) {
        int k = i >> 6, n = (i & 63) * 2;
        uint32_t p; PACK_BF16X2(p, W2[k * H + n], W2[k * H + n + 1]);
        *(uint32_t*)(smem + EB2 + (k * EBS + n) * 2) = p;
    }
    if (tid < 128) { b1v[tid] = b1[tid]; b2v[tid] = b2[tid]; }
    __syncthreads();

    const int lrow = lane & 15;
    const int lk8 = (lane >> 4) << 3;
    uint32_t aA1[2], aA2[2], aB1[2], aB2[2];
#pragma unroll
    for (int mt = 0; mt < 2; mt++) {
        aA1[mt] = sb + EA1  + ((mb + mt * 16 + lrow) * EA1S + lk8) * 2;
        aA2[mt] = sb + EA2_ + ((mb + mt * 16 + lrow) * EA2S + lk8) * 2;
    }
#pragma unroll
    for (int jp = 0; jp < 2; jp++) {
        aB1[jp] = sb + EB1 + (lrow * EBS + nb + jp * 16 + lk8) * 2;
        aB2[jp] = sb + EB2 + (lrow * EBS + nb + jp * 16 + lk8) * 2;
    }

    const float delta = CUTOFF / (float)(R - 1);
    const float coeff = -0.5f / (delta * delta);

    int buf = 0;
    for (int tile = blockIdx.x; tile < N_ETC; tile += gridDim.x, buf ^= 1) {
        int e0 = tile * ETILE;
        if (tid < 128) {
            cs[buf * 128 + tid] = g_C[e0 + tid];
            ss[buf * 128 + tid] = ei[e0 + tid];
            ts[buf * 128 + tid] = ei[N_EDGES + e0 + tid];
        }
        {
            int e = tid >> 2;
            int k0 = (tid & 3) * 16;
            float dv = g_d[e0 + e];
#pragma unroll
            for (int kp = 0; kp < 8; kp++) {
                int k = k0 + 2 * kp;
                float v0 = 0.f, v1 = 0.f;
                if (k < R)     { float u = dv - (float)k * delta;       v0 = __expf(coeff * u * u); }
                if (k + 1 < R) { float u = dv - (float)(k + 1) * delta; v1 = __expf(coeff * u * u); }
                uint32_t p; PACK_BF16X2(p, v0, v1);
                *(uint32_t*)(smem + EA1 + (e * EA1S + k) * 2) = p;
            }
        }
        __syncthreads();   // sync1

        float acc[2][4][4];
        bf16_gemm<4>(aA1[0], aA1[1], aB1[0], aB1[1], 16 * EBS * 2, b1v, nb, t, acc);
#pragma unroll
        for (int mt = 0; mt < 2; mt++) {
            int r2 = mb + mt * 16 + g;
#pragma unroll
            for (int j = 0; j < 4; j++) {
                int col = nb + j * 8 + 2 * t;
                uint32_t p0, p1;
                PACK_BF16X2(p0, ftanh(acc[mt][j][0]), ftanh(acc[mt][j][1]));
                PACK_BF16X2(p1, ftanh(acc[mt][j][2]), ftanh(acc[mt][j][3]));
                *(uint32_t*)(smem + EA2_ + (r2 * EA2S + col) * 2) = p0;
                *(uint32_t*)(smem + EA2_ + ((r2 + 8) * EA2S + col) * 2) = p1;
            }
        }
        __syncthreads();   // sync2

        bf16_gemm<8>(aA2[0], aA2[1], aB2[0], aB2[1], 16 * EBS * 2, b2v, nb, t, acc);

#pragma unroll
        for (int mt = 0; mt < 2; mt++)
#pragma unroll
            for (int half = 0; half < 2; half++) {
                int row = mb + mt * 16 + half * 8 + g;
                float c = cs[buf * 128 + row];
                if (c != 0.0f) {
                    const float* hp = g_h + (size_t)ss[buf * 128 + row] * H + nb;
                    float* ap = g_agg + (size_t)ts[buf * 128 + row] * H + nb;
#pragma unroll
                    for (int j = 0; j < 4; j++) {
                        int o = j * 8 + 2 * t;
                        float2 h2 = *(const float2*)(hp + o);
                        REDV2(ap + o, acc[mt][j][half * 2 + 0] * c * h2.x,
                                      acc[mt][j][half * 2 + 1] * c * h2.y);
                    }
                }
            }
    }
}

// ---- update (bf16, 2 CTA/SM): x += tanh(agg@lin2+b1)@blk + b2 ----
// lin1 mode: + fused lin1_next GEMM -> g_h (W3 reuses NW1 after GEMM1).
// final mode: + fp32 output head from smem-staged x_new -> atomicAdd(out).
__global__ __launch_bounds__(512, 2) void update_bf16(
        const float* __restrict__ lin2_w, const float* __restrict__ lin2_b,
        const float* __restrict__ blk_w, const float* __restrict__ blk_b,
        const float* __restrict__ lin1n_w,
        const float* __restrict__ ow1, const float* __restrict__ ob1,
        const float* __restrict__ ow2, const float* __restrict__ ob2v,
        const int* __restrict__ batch, float* __restrict__ outp) {
    extern __shared__ char smem[];
    float* b1v = (float*)(smem + NB1V);
    float* b2v = (float*)(smem + NB2V);
    float* zb  = (float*)(smem + NZB);
    const uint32_t sb = smem_u32(smem);
    const int tid = threadIdx.x;
    const int wid = tid >> 5, lane = tid & 31;
    const int g = lane >> 2, t = lane & 3;
    const int mb = (wid & 3) * 32, nb = (wid >> 2) * 32;
    const int lrow = lane & 15, lk8 = (lane >> 4) << 3;
    const bool has_lin1 = (lin1n_w != nullptr);

    fill_wbf16(smem, NW1, lin2_w, tid);
    fill_wbf16(smem, NW2, blk_w, tid);
    if (tid < 128) { b1v[tid] = lin2_b[tid]; b2v[tid] = blk_b[tid]; zb[tid] = 0.0f; }
    int a0 = blockIdx.x * TILE_A;
    fill_abf16(smem, NA, g_agg, a0, tid);
    __syncthreads();

    for (int i = tid; i < TILE_A * 32; i += 512) {
        int r = i >> 5, c = i & 31;
        if (a0 + r < N_ATOMS) {
            float4 z; z.x = z.y = z.z = z.w = 0.f;
            ((float4*)g_agg)[(size_t)(a0 + r) * 32 + c] = z;
        }
    }

    uint32_t aA0 = sb + NA + ((mb + lrow) * NBS + lk8) * 2;
    uint32_t aA1 = sb + NA + ((mb + 16 + lrow) * NBS + lk8) * 2;
    uint32_t aW1_0 = sb + NW1 + (lrow * NBS + nb + lk8) * 2;
    uint32_t aW1_1 = sb + NW1 + (lrow * NBS + nb + 16 + lk8) * 2;
    uint32_t aW2_0 = sb + NW2 + (lrow * NBS + nb + lk8) * 2;
    uint32_t aW2_1 = sb + NW2 + (lrow * NBS + nb + 16 + lk8) * 2;
    const int bstep = 16 * NBS * 2;

    float acc[2][4][4];
    // GEMM1: agg @ lin2 + b1
    bf16_gemm<8>(aA0, aA1, aW1_0, aW1_1, bstep, b1v, nb, t, acc);
    __syncthreads();

    // tanh -> NA; overwrite NW1 with lin1_next (disjoint; lin2 dead)
#pragma unroll
    for (int mt = 0; mt < 2; mt++) {
        int r = mb + mt * 16 + g;
#pragma unroll
        for (int j = 0; j < 4; j++) {
            int col = nb + j * 8 + 2 * t;
            uint32_t p0, p1;
            PACK_BF16X2(p0, ftanh(acc[mt][j][0]), ftanh(acc[mt][j][1]));
            PACK_BF16X2(p1, ftanh(acc[mt][j][2]), ftanh(acc[mt][j][3]));
            *(uint32_t*)(smem + NA + (r * NBS + col) * 2) = p0;
            *(uint32_t*)(smem + NA + ((r + 8) * NBS + col) * 2) = p1;
        }
    }
    if (has_lin1) fill_wbf16(smem, NW1, lin1n_w, tid);
    __syncthreads();

    // GEMM2: t @ blk + b2
    bf16_gemm<8>(aA0, aA1, aW2_0, aW2_1, bstep, b2v, nb, t, acc);
    __syncthreads();   // all smem reads (NA, NW2, biases) complete

    if (has_lin1) {
        // x_new = x + acc -> g_x (fp32) and NA (bf16) for GEMM3
#pragma unroll
        for (int mt = 0; mt < 2; mt++)
#pragma unroll
            for (int half = 0; half < 2; half++) {
                int row = mb + mt * 16 + half * 8 + g;
                bool valid = (a0 + row < N_ATOMS);
                float* xp = valid ? g_x + (size_t)(a0 + row) * H : nullptr;
#pragma unroll
                for (int j = 0; j < 4; j++) {
                    int col = nb + j * 8 + 2 * t;
                    float nx = 0.f, ny = 0.f;
                    if (valid) {
                        float2 xv = *(const float2*)(xp + col);
                        nx = xv.x + acc[mt][j][half * 2 + 0];
                        ny = xv.y + acc[mt][j][half * 2 + 1];
                        float2 o; o.x = nx; o.y = ny;
                        *(float2*)(xp + col) = o;
                    }
                    uint32_t p; PACK_BF16X2(p, nx, ny);
                    *(uint32_t*)(smem + NA + (row * NBS + col) * 2) = p;
                }
            }
        __syncthreads();

        // GEMM3: x_new @ lin1_next (NW1) -> g_h
        bf16_gemm<8>(aA0, aA1, aW1_0, aW1_1, bstep, zb, nb, t, acc);
#pragma unroll
        for (int mt = 0; mt < 2; mt++)
#pragma unroll
            for (int half = 0; half < 2; half++) {
                int row = mb + mt * 16 + half * 8 + g;
                if (a0 + row < N_ATOMS) {
                    float* hp = g_h + (size_t)(a0 + row) * H;
#pragma unroll
                    for (int j = 0; j < 4; j++) {
                        int col = nb + j * 8 + 2 * t;
                        float2 v; v.x = acc[mt][j][half * 2]; v.y = acc[mt][j][half * 2 + 1];
                        *(float2*)(hp + col) = v;
                    }
                }
            }
    } else {
        // ---- final mode: fp32 output head, all smem scratch is dead ----
        float* xs = (float*)smem;                 // [128][XSTR] fp32 (67584 B <= NW1+NW2)
        float* ws = (float*)(smem + NA);          // out_w1 [128][64] fp32 (32768 B)
        // stage x_new fp32 (no g_x write needed)
#pragma unroll
        for (int mt = 0; mt < 2; mt++)
#pragma unroll
            for (int half = 0; half < 2; half++) {
                int row = mb + mt * 16 + half * 8 + g;
                bool valid = (a0 + row < N_ATOMS);
                const float* xp = valid ? g_x + (size_t)(a0 + row) * H : nullptr;
#pragma unroll
                for (int j = 0; j < 4; j++) {
                    int col = nb + j * 8 + 2 * t;
                    float nx = 0.f, ny = 0.f;
                    if (valid) {
                        float2 xv = *(const float2*)(xp + col);
                        nx = xv.x + acc[mt][j][half * 2 + 0];
                        ny = xv.y + acc[mt][j][half * 2 + 1];
                    }
                    float2 o; o.x = nx; o.y = ny;
                    *(float2*)&xs[row * XSTR + col] = o;
                }
            }
        // load out-head params (biases dead now)
        for (int i = tid; i < 128 * 64; i += 512) ws[i] = ow1[i];
        if (tid < 64) { b1v[tid] = ob1[tid]; b2v[tid] = ow2[tid]; }
        __syncthreads();

        float ob2 = ob2v[0];
        // each warp: 8 rows; lane covers out-cols {lane, lane+32}
#pragma unroll
        for (int rr = 0; rr < 8; rr++) {
            int row = wid * 8 + rr;
            int a = a0 + row;
            float s0 = b1v[lane], s1 = b1v[lane + 32];
            const float* xr = &xs[row * XSTR];
#pragma unroll 4
            for (int k = 0; k < H; k++) {
                float xk = xr[k];
                s0 = fmaf(xk, ws[k * 64 + lane], s0);
                s1 = fmaf(xk, ws[k * 64 + lane + 32], s1);
            }
            float part = ftanh(s0) * b2v[lane] + ftanh(s1) * b2v[lane + 32];
#pragma unroll
            for (int off = 16; off; off >>= 1)
                part += __shfl_down_sync(0xffffffffu, part, off);
            if (lane == 0 && a < N_ATOMS)
                atomicAdd(&outp[batch[a]], part + ob2);
        }
    }
}

// ---------------- output zero ----------------
__global__ void zero_out_kernel(float* out) {
    if (threadIdx.x < NEX) out[threadIdx.x] = 0.0f;
}

// ---------------- host launcher ----------------
extern "C" void kernel_launch(void* const* d_in, const int* in_sizes, int n_in,
                              void* d_out, int out_size) {
    const float* pos        = (const float*)d_in[0];
    const int*   atom_types = (const int*)  d_in[1];
    const int*   edge_index = (const int*)  d_in[2];
    const int*   batch      = (const int*)  d_in[3];
    const float* embedding  = (const float*)d_in[4];
    const float* filt_w1    = (const float*)d_in[5];
    const float* filt_b1    = (const float*)d_in[6];
    const float* filt_w2    = (const float*)d_in[7];
    const float* filt_b2    = (const float*)d_in[8];
    const float* lin1_w     = (const float*)d_in[9];
    const float* lin2_w     = (const float*)d_in[10];
    const float* lin2_b     = (const float*)d_in[11];
    const float* blk_w      = (const float*)d_in[12];
    const float* blk_b      = (const float*)d_in[13];
    const float* out_w1     = (const float*)d_in[14];
    const float* out_b1     = (const float*)d_in[15];
    const float* out_w2     = (const float*)d_in[16];
    const float* out_b2     = (const float*)d_in[17];
    float* out = (float*)d_out;

    cudaFuncSetAttribute(edge_bf16_kernel, cudaFuncAttributeMaxDynamicSharedMemorySize, SMB_EDGE);
    cudaFuncSetAttribute(lin1_bf16,        cudaFuncAttributeMaxDynamicSharedMemorySize, SMB_LIN1);
    cudaFuncSetAttribute(update_bf16,      cudaFuncAttributeMaxDynamicSharedMemorySize, SMB_UPD);

    geom_kernel<<<(N_EDGES + 255) / 256, 256>>>(pos, edge_index);
    lin1_bf16<<<N_ATILES, 512, SMB_LIN1>>>(atom_types, embedding, lin1_w);

    for (int b = 0; b < NB; b++) {
        edge_bf16_kernel<<<296, 512, SMB_EDGE>>>(filt_w1 + b * R * H, filt_b1 + b * H,
                                                 filt_w2 + b * H * H, filt_b2 + b * H,
                                                 edge_index);
        if (b + 1 < NB) {
            update_bf16<<<N_ATILES, 512, SMB_UPD>>>(lin2_w + b * H * H, lin2_b + b * H,
                                                    blk_w + b * H * H, blk_b + b * H,
                                                    lin1_w + (b + 1) * H * H,
                                                    nullptr, nullptr, nullptr, nullptr,
                                                    nullptr, nullptr);
        } else {
            zero_out_kernel<<<1, 64>>>(out);
            update_bf16<<<N_ATILES, 512, SMB_UPD>>>(lin2_w + b * H * H, lin2_b + b * H,
                                                    blk_w + b * H * H, blk_b + b * H,
                                                    nullptr,
                                                    out_w1, out_b1, out_w2, out_b2,
                                                    batch, out);
        }
    }
}